// round 16
// baseline (speedup 1.0000x reference)
#include <cuda_runtime.h>
#include <cstdint>

#define BB 8
#define HH 4
#define LL 2048
#define DD 128
#define DKK 32

// (1/sqrt(32)) * log2(e): softmax runs in exp2 domain
__device__ constexpr float QSCALE = (float)(0.17677669529663689 * 1.4426950408889634);
#define SHIFT 12.0f
#define P_PAD 0.000244140625f     // exp2(-12), exact

// Scratch. g_x: tf32 x with l-pairing permutation.
// Compacted per (b,h), stride 2048 rows: g_q (pre-scaled), g_k, g_v grouped.
// g_head: (b,l,h*32+dk) tf32; masked rows zeroed by conv.
__device__ float g_x[BB*LL*DD];
__device__ float g_q[BB*HH*LL*DKK];
__device__ float g_k[BB*HH*LL*DKK];
__device__ float g_v[BB*HH*LL*DKK];
__device__ float g_head[BB*LL*DD];
__device__ int   g_idx1[BB*LL];
__device__ int   g_rank[BB*LL];
__device__ int   g_cnt[2*BB];

__device__ __forceinline__ int permk(int k){           // pair (k, k+4) adjacent
    return (k & ~7) | (2*(k & 3) + ((k & 7) >> 2));
}
__device__ __forceinline__ uint32_t f2tf(float x){
    uint32_t u; asm("cvt.rna.tf32.f32 %0, %1;" : "=r"(u) : "f"(x)); return u;
}
__device__ __forceinline__ float f2tff(float x){ return __uint_as_float(f2tf(x)); }
__device__ __forceinline__ float ex2(float x){
    float y; asm("ex2.approx.f32 %0, %1;" : "=f"(y) : "f"(x)); return y;
}
__device__ __forceinline__ void mma8(float* d, const uint32_t* a, uint32_t b0, uint32_t b1){
    asm volatile("mma.sync.aligned.m16n8k8.row.col.f32.tf32.tf32.f32 "
        "{%0,%1,%2,%3},{%4,%5,%6,%7},{%8,%9},{%0,%1,%2,%3};"
        : "+f"(d[0]),"+f"(d[1]),"+f"(d[2]),"+f"(d[3])
        : "r"(a[0]),"r"(a[1]),"r"(a[2]),"r"(a[3]), "r"(b0),"r"(b1));
}
__device__ __forceinline__ void cpa16(void* dst_smem, const void* src){
    uint32_t d = (uint32_t)__cvta_generic_to_shared(dst_smem);
    asm volatile("cp.async.ca.shared.global [%0], [%1], 16;" :: "r"(d), "l"(src));
}
__device__ __forceinline__ void cpa_commit(){ asm volatile("cp.async.commit_group;"); }
template<int N> __device__ __forceinline__ void cpa_wait(){
    asm volatile("cp.async.wait_group %0;" :: "n"(N));
}

// ---------------------------------------------------------------------------
// Kernel 1: per-batch compaction scan (runs FIRST).
// ---------------------------------------------------------------------------
__global__ __launch_bounds__(256) void scan_kernel(const float* __restrict__ mask)
{
    const int b = blockIdx.x, t = threadIdx.x;
    __shared__ int sc[256];
    int m[8]; int c1 = 0;
    #pragma unroll
    for (int i = 0; i < 8; i++) {
        m[i] = (mask[b*LL + t*8 + i] > 0.5f) ? 1 : 0;
        c1 += m[i];
    }
    sc[t] = c1; __syncthreads();
    for (int off = 1; off < 256; off <<= 1) {
        int v = (t >= off) ? sc[t-off] : 0;
        __syncthreads();
        sc[t] += v;
        __syncthreads();
    }
    const int inc1 = sc[t];
    const int ex1  = inc1 - c1;
    const int tot1 = sc[255];
    int r1 = ex1, r0 = t*8 - ex1;
    #pragma unroll
    for (int i = 0; i < 8; i++) {
        int l = t*8 + i;
        if (m[i]) { g_idx1[b*LL + r1] = l; g_rank[b*LL + l] = r1; r1++; }
        else      {                        g_rank[b*LL + l] = r0; r0++; }
    }
    if (t == 0) { g_cnt[2*b+1] = tot1; g_cnt[2*b] = LL - tot1; }
}

// ---------------------------------------------------------------------------
// Kernel 0: x -> tf32 l-paired into g_x; zero masked g_head rows; first 32
// blocks additionally zero the compacted pad slots (scan ran already).
// ---------------------------------------------------------------------------
__global__ __launch_bounds__(256) void conv_kernel(
    const float* __restrict__ x, const float* __restrict__ mask)
{
    size_t i = (size_t)blockIdx.x * 256 + threadIdx.x;    // float4 index
    float4 v = reinterpret_cast<const float4*>(x)[i];
    size_t f = i * 4;
    size_t row = f >> 11;
    int l = (int)(f & 2047);
    int base = (l & ~15) | ((l & 7) << 1) | ((l >> 3) & 1);
    float* dst = g_x + row*LL + base;
    dst[0] = f2tff(v.x); dst[2] = f2tff(v.y);
    dst[4] = f2tff(v.z); dst[6] = f2tff(v.w);

    size_t hrow = f >> 7;
    int hb = (int)(hrow >> 11), hl = (int)(hrow & 2047);
    if (mask[hb*LL + hl] < 0.5f)
        reinterpret_cast<float4*>(g_head)[i] = make_float4(0.f,0.f,0.f,0.f);

    // Pad-zeroing: one (b,h) per early block
    if (blockIdx.x < BB*HH) {
        const int bh = blockIdx.x;
        const int b  = bh >> 2;
        const int t  = threadIdx.x;
        const int c1 = g_cnt[2*b+1], c0 = g_cnt[2*b];
        const int p1 = (c1 + 127) & ~127, p0 = (c0 + 127) & ~127;
        for (int j = t; j < (p1 - c1)*DKK; j += 256) {
            int r = c1 + j/DKK, k = j % DKK;
            g_q[((size_t)bh*LL + r)*DKK + k] = 0.f;
        }
        for (int j = t; j < (p0 - c0)*DKK; j += 256) {
            int r = c0 + j/DKK, k = j % DKK;
            g_k[((size_t)bh*LL + r)*DKK + k] = 0.f;
            g_v[(size_t)bh*(LL*DKK) + (r>>3)*256 + k*8 + (r&7)] = 0.f;
        }
    }
}

// ---------------------------------------------------------------------------
// Kernel A: QKV projection (unchanged from R15), compacted epilogue.
// ---------------------------------------------------------------------------
struct QSmem {
    uint32_t As[2][32][136];
    uint32_t Ws[3][64][136];
};
extern __shared__ float qsm_f[];

__global__ __launch_bounds__(256) void qkv_kernel(
    const float* __restrict__ Wq, const float* __restrict__ Wk,
    const float* __restrict__ Wv, const float* __restrict__ mask)
{
    QSmem& S = *reinterpret_cast<QSmem*>(qsm_f);
    const float* __restrict__ xt = g_x;
    const int half = blockIdx.x;
    const int m0   = blockIdx.y * 128;
    const int b    = m0 >> 11;
    const int l0   = m0 & 2047;
    const int t    = threadIdx.x;
    const int lane = t & 31, wid = t >> 5;
    const int g = lane >> 2, tg = lane & 3, r0 = wid * 16;

    #pragma unroll
    for (int mat = 0; mat < 3; mat++) {
        const float* __restrict__ w = (mat==0) ? Wq : ((mat==1) ? Wk : Wv);
        #pragma unroll
        for (int i = 0; i < 32; i++) {
            int el = t + i*256;
            int k  = el >> 6, n = el & 63;
            int ng = half*64 + n;
            S.Ws[mat][n][permk(k)] = f2tf(w[((ng>>5)*DD + k)*DKK + (ng & 31)]);
        }
    }
    #pragma unroll
    for (int i = 0; i < 4; i++) {
        int ch = t + i*256;
        int row = ch >> 5, off = (ch & 31)*4;
        cpa16(&S.As[0][row][off], xt + ((size_t)(b*DD + row))*LL + l0 + off);
    }
    cpa_commit();
    __syncthreads();

    float acc[3][8][4] = {};
    for (int c4 = 0; c4 < 4; c4++) {
        const int dbuf = c4 & 1;
        if (c4) __syncthreads();
        if (c4 + 1 < 4) {
            int k0n = (c4+1)*32, dn = (c4+1)&1;
            #pragma unroll
            for (int i = 0; i < 4; i++) {
                int ch = t + i*256;
                int row = ch >> 5, off = (ch & 31)*4;
                cpa16(&S.As[dn][row][off], xt + ((size_t)(b*DD + k0n + row))*LL + l0 + off);
            }
            cpa_commit();
            cpa_wait<1>();
        } else cpa_wait<0>();
        __syncthreads();

        #pragma unroll
        for (int kg4 = 0; kg4 < 4; kg4++) {
            const int kr = kg4*8;
            uint2 a01 = *reinterpret_cast<uint2*>(&S.As[dbuf][kr+tg  ][r0 + 2*g]);
            uint2 a23 = *reinterpret_cast<uint2*>(&S.As[dbuf][kr+tg+4][r0 + 2*g]);
            uint32_t a[4] = {a01.x, a01.y, a23.x, a23.y};
            #pragma unroll
            for (int mat = 0; mat < 3; mat++)
                #pragma unroll
                for (int nt = 0; nt < 8; nt++) {
                    uint2 bv = *reinterpret_cast<uint2*>(
                        &S.Ws[mat][nt*8+g][c4*32 + kr + 2*tg]);
                    mma8(acc[mat][nt], a, bv.x, bv.y);
                }
        }
    }

    const int l_a = l0 + r0 + g;
    const int l_b = l_a + 8;
    const bool qA = mask[b*LL + l_a] > 0.5f;
    const bool qB = mask[b*LL + l_b] > 0.5f;
    const int rkA = g_rank[b*LL + l_a];
    const int rkB = g_rank[b*LL + l_b];

    #pragma unroll
    for (int mat = 0; mat < 3; mat++) {
        const float sc = (mat == 0) ? QSCALE : 1.0f;
        #pragma unroll
        for (int nt = 0; nt < 8; nt++) {
            #pragma unroll
            for (int u = 0; u < 4; u++) {
                int n = half*64 + nt*8 + 2*tg + (u & 1);
                bool second = (u >> 1);
                int slot = second ? rkB : rkA;
                bool isQ  = second ? qB  : qA;
                int h = n >> 5, dk = n & 31;
                size_t bh = (size_t)(b*HH + h);
                float val = f2tff(acc[mat][nt][u] * sc);
                if (mat == 0) {
                    if (isQ)  g_q[(bh*LL + slot)*DKK + permk(dk)] = val;
                } else if (mat == 1) {
                    if (!isQ) g_k[(bh*LL + slot)*DKK + permk(dk)] = val;
                } else {
                    if (!isQ) g_v[bh*(LL*DKK) + (slot>>3)*256 + dk*8 + (slot&7)] = val;
                }
            }
        }
    }
}

// ---------------------------------------------------------------------------
// Kernel B: compacted flash attention. 64-row q-tiles (grid 1024, full chip)
// with 2 warps x 32 rows (2-strip): every K/V fragment feeds 2 mmas.
// ---------------------------------------------------------------------------
struct ASmem {
    float Ks[2][64][40];
    float Vs[2][2048];
};

__global__ __launch_bounds__(64, 6) void attn_kernel()
{
    const int b = blockIdx.z, h = blockIdx.y, q0 = blockIdx.x * 64;
    const int cnt0 = g_cnt[2*b], cnt1 = g_cnt[2*b+1];
    const int npad1 = (cnt1 + 63) & ~63;
    if (q0 >= npad1) return;
    const int NT = (cnt0 + 63) >> 6;
    const float padcorr = (float)(NT*64 - cnt0) * P_PAD;

    __shared__ ASmem S;
    const int t = threadIdx.x, lane = t & 31, wid = t >> 5;
    const int g = lane >> 2, tg = lane & 3, r0 = wid * 32;

    const float* __restrict__ Qg = g_q + ((size_t)(b*HH+h))*LL*DKK;
    const float* __restrict__ Kg = g_k + ((size_t)(b*HH+h))*LL*DKK;
    const float* __restrict__ Vg = g_v + ((size_t)(b*HH+h))*LL*DKK;

    // Prefetch tile 0 (64 threads: 8 iterations each for K and V)
    #pragma unroll
    for (int i = 0; i < 8; i++) {
        int ch = t + i*64;
        { int row = ch >> 3, off = (ch & 7)*4;
          cpa16(&S.Ks[0][row][off], Kg + row*DKK + off); }
        cpa16(&S.Vs[0][ch*4], Vg + ch*4);
    }
    cpa_commit();

    // Q fragments (2 strips of 16 rows per warp)
    uint32_t aQ[2][4][4];
    #pragma unroll
    for (int s = 0; s < 2; s++)
        #pragma unroll
        for (int kg4 = 0; kg4 < 4; kg4++) {
            float2 x0 = *reinterpret_cast<const float2*>(
                &Qg[(q0 + r0 + s*16 + g    )*DKK + kg4*8 + 2*tg]);
            float2 x1 = *reinterpret_cast<const float2*>(
                &Qg[(q0 + r0 + s*16 + g + 8)*DKK + kg4*8 + 2*tg]);
            aQ[s][kg4][0] = __float_as_uint(x0.x);
            aQ[s][kg4][1] = __float_as_uint(x1.x);
            aQ[s][kg4][2] = __float_as_uint(x0.y);
            aQ[s][kg4][3] = __float_as_uint(x1.y);
        }

    float o[2][4][4] = {};
    float l[2][2] = {};

    for (int kt = 0; kt < NT; kt++) {
        const int d = kt & 1;
        __syncthreads();
        if (kt + 1 < NT) {
            const int c0n = (kt+1)*64, dn = (kt+1)&1;
            #pragma unroll
            for (int i = 0; i < 8; i++) {
                int ch = t + i*64;
                { int row = ch >> 3, off = (ch & 7)*4;
                  cpa16(&S.Ks[dn][row][off], Kg + (c0n+row)*DKK + off); }
                cpa16(&S.Vs[dn][ch*4], Vg + (kt+1)*2048 + ch*4);
            }
            cpa_commit();
            cpa_wait<1>();
        } else cpa_wait<0>();
        __syncthreads();

        #pragma unroll
        for (int j = 0; j < 8; j++) {
            float accS[2][4] = {};
            #pragma unroll
            for (int kg4 = 0; kg4 < 4; kg4++) {
                float2 bv = *reinterpret_cast<float2*>(&S.Ks[d][j*8+g][kg4*8+2*tg]);
                mma8(accS[0], aQ[0][kg4], __float_as_uint(bv.x), __float_as_uint(bv.y));
                mma8(accS[1], aQ[1][kg4], __float_as_uint(bv.x), __float_as_uint(bv.y));
            }
            uint32_t aP[2][4];
            #pragma unroll
            for (int s = 0; s < 2; s++) {
                float p0 = ex2(accS[s][0]-SHIFT);
                float p1 = ex2(accS[s][1]-SHIFT);
                float p2 = ex2(accS[s][2]-SHIFT);
                float p3 = ex2(accS[s][3]-SHIFT);
                l[s][0] += p0 + p1;  l[s][1] += p2 + p3;
                aP[s][0] = __float_as_uint(p0);
                aP[s][1] = __float_as_uint(p2);
                aP[s][2] = __float_as_uint(p1);
                aP[s][3] = __float_as_uint(p3);
            }
            #pragma unroll
            for (int nt = 0; nt < 4; nt++) {
                float2 bv = *reinterpret_cast<float2*>(&S.Vs[d][j*256 + (nt*8+g)*8 + 2*tg]);
                mma8(o[0][nt], aP[0], __float_as_uint(bv.x), __float_as_uint(bv.y));
                mma8(o[1][nt], aP[1], __float_as_uint(bv.x), __float_as_uint(bv.y));
            }
        }
    }

    // ---- epilogue ----
    #pragma unroll
    for (int s = 0; s < 2; s++) {
        float l0 = l[s][0], l1 = l[s][1];
        l0 += __shfl_xor_sync(~0u, l0, 1);  l0 += __shfl_xor_sync(~0u, l0, 2);
        l1 += __shfl_xor_sync(~0u, l1, 1);  l1 += __shfl_xor_sync(~0u, l1, 2);
        l0 -= padcorr;  l1 -= padcorr;
        int rq = q0 + r0 + s*16 + g;
        if (rq < cnt1) {
            int lq = g_idx1[b*LL + rq];
            float inv = 1.0f / l0;
            float* __restrict__ H = &g_head[((size_t)(b*LL + lq))*DD + h*DKK];
            #pragma unroll
            for (int nt = 0; nt < 4; nt++)
                *reinterpret_cast<float2*>(&H[nt*8+2*tg]) =
                    make_float2(f2tff(o[s][nt][0]*inv), f2tff(o[s][nt][1]*inv));
        }
        if (rq + 8 < cnt1) {
            int lq = g_idx1[b*LL + rq + 8];
            float inv = 1.0f / l1;
            float* __restrict__ H = &g_head[((size_t)(b*LL + lq))*DD + h*DKK];
            #pragma unroll
            for (int nt = 0; nt < 4; nt++)
                *reinterpret_cast<float2*>(&H[nt*8+2*tg]) =
                    make_float2(f2tff(o[s][nt][2]*inv), f2tff(o[s][nt][3]*inv));
        }
    }
}

// ---------------------------------------------------------------------------
// Kernel C: output projection (unchanged from R15).
// ---------------------------------------------------------------------------
struct OSmem {
    float    As[2][128][36];
    uint32_t Bs[128][72];
};
extern __shared__ uint32_t osm_u[];

__global__ __launch_bounds__(256, 3) void out_kernel(
    const float* __restrict__ Wo, float* __restrict__ out)
{
    OSmem& S = *reinterpret_cast<OSmem*>(osm_u);
    const int half = blockIdx.x;
    const int m0   = blockIdx.y * 128;
    const int b    = m0 >> 11;
    const int l0   = m0 & 2047;
    const int t    = threadIdx.x;
    const int lane = t & 31, wid = t >> 5;
    const int g = lane >> 2, tg = lane & 3, r0 = wid * 16;

    #pragma unroll
    for (int i = 0; i < 8; i++) {
        int fid = t + i*256;
        int n4 = fid & 15, kk = fid >> 4;
        float4 v4 = *reinterpret_cast<const float4*>(&Wo[kk*DD + half*64 + n4*4]);
        uint4 u; u.x=f2tf(v4.x); u.y=f2tf(v4.y); u.z=f2tf(v4.z); u.w=f2tf(v4.w);
        *reinterpret_cast<uint4*>(&S.Bs[kk][n4*4]) = u;
    }
    #pragma unroll
    for (int i = 0; i < 4; i++) {
        int ch = t + i*256;
        int mm = ch >> 3, off = (ch & 7)*4;
        cpa16(&S.As[0][mm][off], &g_head[(((size_t)(b*LL)) + l0 + mm)*DD + off]);
    }
    cpa_commit();
    __syncthreads();

    float acc[8][4] = {};
    for (int c4 = 0; c4 < 4; c4++) {
        const int dbuf = c4 & 1;
        if (c4) __syncthreads();
        if (c4 + 1 < 4) {
            int k0n = (c4+1)*32, dn = (c4+1)&1;
            #pragma unroll
            for (int i = 0; i < 4; i++) {
                int ch = t + i*256;
                int mm = ch >> 3, off = (ch & 7)*4;
                cpa16(&S.As[dn][mm][off],
                      &g_head[(((size_t)(b*LL)) + l0 + mm)*DD + k0n + off]);
            }
            cpa_commit();
            cpa_wait<1>();
        } else cpa_wait<0>();
        __syncthreads();

        #pragma unroll
        for (int kg4 = 0; kg4 < 4; kg4++) {
            const int kr = kg4*8;
            uint32_t a[4] = {__float_as_uint(S.As[dbuf][r0+g  ][kr+tg]),
                             __float_as_uint(S.As[dbuf][r0+g+8][kr+tg]),
                             __float_as_uint(S.As[dbuf][r0+g  ][kr+tg+4]),
                             __float_as_uint(S.As[dbuf][r0+g+8][kr+tg+4])};
            #pragma unroll
            for (int nt = 0; nt < 8; nt++)
                mma8(acc[nt], a, S.Bs[c4*32+kr+tg][nt*8+g],
                                 S.Bs[c4*32+kr+tg+4][nt*8+g]);
        }
    }
    __syncthreads();

    float (*Cs)[132] = reinterpret_cast<float (*)[132]>(&S.As[0][0][0]);
    #pragma unroll
    for (int nt = 0; nt < 8; nt++) {
        Cs[nt*8+2*tg  ][r0+g  ] = acc[nt][0];
        Cs[nt*8+2*tg+1][r0+g  ] = acc[nt][1];
        Cs[nt*8+2*tg  ][r0+g+8] = acc[nt][2];
        Cs[nt*8+2*tg+1][r0+g+8] = acc[nt][3];
    }
    __syncthreads();
    #pragma unroll
    for (int i = 0; i < 8; i++) {
        int fid = t + i*256;
        int m4 = fid & 31, nn = fid >> 5;
        float4 v4 = *reinterpret_cast<const float4*>(&Cs[nn][m4*4]);
        *reinterpret_cast<float4*>(
            &out[((size_t)(b*DD + half*64 + nn))*LL + l0 + m4*4]) = v4;
    }
}

// ---------------------------------------------------------------------------
extern "C" void kernel_launch(void* const* d_in, const int* in_sizes, int n_in,
                              void* d_out, int out_size)
{
    const float* x    = (const float*)d_in[0];
    const float* mask = (const float*)d_in[1];
    const float* Wq   = (const float*)d_in[2];
    const float* Wk   = (const float*)d_in[3];
    const float* Wv   = (const float*)d_in[4];
    const float* Wo   = (const float*)d_in[5];
    float* out = (float*)d_out;

    scan_kernel<<<BB, 256>>>(mask);
    conv_kernel<<<(BB*DD*LL)/4/256, 256>>>(x, mask);

    cudaFuncSetAttribute(qkv_kernel, cudaFuncAttributeMaxDynamicSharedMemorySize,
                         (int)sizeof(QSmem));
    dim3 gA(2, (BB*LL)/128);
    qkv_kernel<<<gA, 256, sizeof(QSmem)>>>(Wq, Wk, Wv, mask);

    dim3 gB(LL/64, HH, BB);
    attn_kernel<<<gB, 64>>>();

    cudaFuncSetAttribute(out_kernel, cudaFuncAttributeMaxDynamicSharedMemorySize,
                         (int)sizeof(OSmem));
    dim3 gC(2, (BB*LL)/128);
    out_kernel<<<gC, 256, sizeof(OSmem)>>>(Wo, out);
}

// round 17
// speedup vs baseline: 1.1981x; 1.1981x over previous
#include <cuda_runtime.h>
#include <cstdint>

#define BB 8
#define HH 4
#define LL 2048
#define DD 128
#define DKK 32

// (1/sqrt(32)) * log2(e): softmax runs in exp2 domain
__device__ constexpr float QSCALE = (float)(0.17677669529663689 * 1.4426950408889634);
#define SHIFT 12.0f
#define P_PAD 0.000244140625f     // exp2(-12), exact

// Scratch. g_x: tf32 x with l-pairing permutation.
// Compacted per (b,h), stride 2048 rows: g_q (pre-scaled), g_k, g_v grouped.
// g_head: (b,l,h*32+dk) tf32; masked rows zeroed by conv.
__device__ float g_x[BB*LL*DD];
__device__ float g_q[BB*HH*LL*DKK];
__device__ float g_k[BB*HH*LL*DKK];
__device__ float g_v[BB*HH*LL*DKK];
__device__ float g_head[BB*LL*DD];
__device__ int   g_idx1[BB*LL];
__device__ int   g_rank[BB*LL];
__device__ int   g_cnt[2*BB];

__device__ __forceinline__ int permk(int k){           // pair (k, k+4) adjacent
    return (k & ~7) | (2*(k & 3) + ((k & 7) >> 2));
}
__device__ __forceinline__ uint32_t f2tf(float x){
    uint32_t u; asm("cvt.rna.tf32.f32 %0, %1;" : "=r"(u) : "f"(x)); return u;
}
__device__ __forceinline__ float f2tff(float x){ return __uint_as_float(f2tf(x)); }
__device__ __forceinline__ float ex2(float x){
    float y; asm("ex2.approx.f32 %0, %1;" : "=f"(y) : "f"(x)); return y;
}
__device__ __forceinline__ void mma8(float* d, const uint32_t* a, uint32_t b0, uint32_t b1){
    asm volatile("mma.sync.aligned.m16n8k8.row.col.f32.tf32.tf32.f32 "
        "{%0,%1,%2,%3},{%4,%5,%6,%7},{%8,%9},{%0,%1,%2,%3};"
        : "+f"(d[0]),"+f"(d[1]),"+f"(d[2]),"+f"(d[3])
        : "r"(a[0]),"r"(a[1]),"r"(a[2]),"r"(a[3]), "r"(b0),"r"(b1));
}
__device__ __forceinline__ void cpa16(void* dst_smem, const void* src){
    uint32_t d = (uint32_t)__cvta_generic_to_shared(dst_smem);
    asm volatile("cp.async.ca.shared.global [%0], [%1], 16;" :: "r"(d), "l"(src));
}
__device__ __forceinline__ void cpa_commit(){ asm volatile("cp.async.commit_group;"); }
template<int N> __device__ __forceinline__ void cpa_wait(){
    asm volatile("cp.async.wait_group %0;" :: "n"(N));
}

// ---------------------------------------------------------------------------
// Kernel 1: per-batch compaction scan (runs FIRST).
// ---------------------------------------------------------------------------
__global__ __launch_bounds__(256) void scan_kernel(const float* __restrict__ mask)
{
    const int b = blockIdx.x, t = threadIdx.x;
    __shared__ int sc[256];
    int m[8]; int c1 = 0;
    #pragma unroll
    for (int i = 0; i < 8; i++) {
        m[i] = (mask[b*LL + t*8 + i] > 0.5f) ? 1 : 0;
        c1 += m[i];
    }
    sc[t] = c1; __syncthreads();
    for (int off = 1; off < 256; off <<= 1) {
        int v = (t >= off) ? sc[t-off] : 0;
        __syncthreads();
        sc[t] += v;
        __syncthreads();
    }
    const int inc1 = sc[t];
    const int ex1  = inc1 - c1;
    const int tot1 = sc[255];
    int r1 = ex1, r0 = t*8 - ex1;
    #pragma unroll
    for (int i = 0; i < 8; i++) {
        int l = t*8 + i;
        if (m[i]) { g_idx1[b*LL + r1] = l; g_rank[b*LL + l] = r1; r1++; }
        else      {                        g_rank[b*LL + l] = r0; r0++; }
    }
    if (t == 0) { g_cnt[2*b+1] = tot1; g_cnt[2*b] = LL - tot1; }
}

// ---------------------------------------------------------------------------
// Kernel 0: x -> tf32 l-paired into g_x; zero masked g_head rows; first 32
// blocks additionally zero the compacted pad slots (scan ran already).
// ---------------------------------------------------------------------------
__global__ __launch_bounds__(256) void conv_kernel(
    const float* __restrict__ x, const float* __restrict__ mask)
{
    size_t i = (size_t)blockIdx.x * 256 + threadIdx.x;    // float4 index
    float4 v = reinterpret_cast<const float4*>(x)[i];
    size_t f = i * 4;
    size_t row = f >> 11;
    int l = (int)(f & 2047);
    int base = (l & ~15) | ((l & 7) << 1) | ((l >> 3) & 1);
    float* dst = g_x + row*LL + base;
    dst[0] = f2tff(v.x); dst[2] = f2tff(v.y);
    dst[4] = f2tff(v.z); dst[6] = f2tff(v.w);

    size_t hrow = f >> 7;
    int hb = (int)(hrow >> 11), hl = (int)(hrow & 2047);
    if (mask[hb*LL + hl] < 0.5f)
        reinterpret_cast<float4*>(g_head)[i] = make_float4(0.f,0.f,0.f,0.f);

    // Pad-zeroing: one (b,h) per early block
    if (blockIdx.x < BB*HH) {
        const int bh = blockIdx.x;
        const int b  = bh >> 2;
        const int t  = threadIdx.x;
        const int c1 = g_cnt[2*b+1], c0 = g_cnt[2*b];
        const int p1 = (c1 + 127) & ~127, p0 = (c0 + 127) & ~127;
        for (int j = t; j < (p1 - c1)*DKK; j += 256) {
            int r = c1 + j/DKK, k = j % DKK;
            g_q[((size_t)bh*LL + r)*DKK + k] = 0.f;
        }
        for (int j = t; j < (p0 - c0)*DKK; j += 256) {
            int r = c0 + j/DKK, k = j % DKK;
            g_k[((size_t)bh*LL + r)*DKK + k] = 0.f;
            g_v[(size_t)bh*(LL*DKK) + (r>>3)*256 + k*8 + (r&7)] = 0.f;
        }
    }
}

// ---------------------------------------------------------------------------
// Kernel A: QKV projection (R15 config), compacted epilogue.
// ---------------------------------------------------------------------------
struct QSmem {
    uint32_t As[2][32][136];
    uint32_t Ws[3][64][136];
};
extern __shared__ float qsm_f[];

__global__ __launch_bounds__(256) void qkv_kernel(
    const float* __restrict__ Wq, const float* __restrict__ Wk,
    const float* __restrict__ Wv, const float* __restrict__ mask)
{
    QSmem& S = *reinterpret_cast<QSmem*>(qsm_f);
    const float* __restrict__ xt = g_x;
    const int half = blockIdx.x;
    const int m0   = blockIdx.y * 128;
    const int b    = m0 >> 11;
    const int l0   = m0 & 2047;
    const int t    = threadIdx.x;
    const int lane = t & 31, wid = t >> 5;
    const int g = lane >> 2, tg = lane & 3, r0 = wid * 16;

    #pragma unroll
    for (int mat = 0; mat < 3; mat++) {
        const float* __restrict__ w = (mat==0) ? Wq : ((mat==1) ? Wk : Wv);
        #pragma unroll
        for (int i = 0; i < 32; i++) {
            int el = t + i*256;
            int k  = el >> 6, n = el & 63;
            int ng = half*64 + n;
            S.Ws[mat][n][permk(k)] = f2tf(w[((ng>>5)*DD + k)*DKK + (ng & 31)]);
        }
    }
    #pragma unroll
    for (int i = 0; i < 4; i++) {
        int ch = t + i*256;
        int row = ch >> 5, off = (ch & 31)*4;
        cpa16(&S.As[0][row][off], xt + ((size_t)(b*DD + row))*LL + l0 + off);
    }
    cpa_commit();
    __syncthreads();

    float acc[3][8][4] = {};
    for (int c4 = 0; c4 < 4; c4++) {
        const int dbuf = c4 & 1;
        if (c4) __syncthreads();
        if (c4 + 1 < 4) {
            int k0n = (c4+1)*32, dn = (c4+1)&1;
            #pragma unroll
            for (int i = 0; i < 4; i++) {
                int ch = t + i*256;
                int row = ch >> 5, off = (ch & 31)*4;
                cpa16(&S.As[dn][row][off], xt + ((size_t)(b*DD + k0n + row))*LL + l0 + off);
            }
            cpa_commit();
            cpa_wait<1>();
        } else cpa_wait<0>();
        __syncthreads();

        #pragma unroll
        for (int kg4 = 0; kg4 < 4; kg4++) {
            const int kr = kg4*8;
            uint2 a01 = *reinterpret_cast<uint2*>(&S.As[dbuf][kr+tg  ][r0 + 2*g]);
            uint2 a23 = *reinterpret_cast<uint2*>(&S.As[dbuf][kr+tg+4][r0 + 2*g]);
            uint32_t a[4] = {a01.x, a01.y, a23.x, a23.y};
            #pragma unroll
            for (int mat = 0; mat < 3; mat++)
                #pragma unroll
                for (int nt = 0; nt < 8; nt++) {
                    uint2 bv = *reinterpret_cast<uint2*>(
                        &S.Ws[mat][nt*8+g][c4*32 + kr + 2*tg]);
                    mma8(acc[mat][nt], a, bv.x, bv.y);
                }
        }
    }

    const int l_a = l0 + r0 + g;
    const int l_b = l_a + 8;
    const bool qA = mask[b*LL + l_a] > 0.5f;
    const bool qB = mask[b*LL + l_b] > 0.5f;
    const int rkA = g_rank[b*LL + l_a];
    const int rkB = g_rank[b*LL + l_b];

    #pragma unroll
    for (int mat = 0; mat < 3; mat++) {
        const float sc = (mat == 0) ? QSCALE : 1.0f;
        #pragma unroll
        for (int nt = 0; nt < 8; nt++) {
            #pragma unroll
            for (int u = 0; u < 4; u++) {
                int n = half*64 + nt*8 + 2*tg + (u & 1);
                bool second = (u >> 1);
                int slot = second ? rkB : rkA;
                bool isQ  = second ? qB  : qA;
                int h = n >> 5, dk = n & 31;
                size_t bh = (size_t)(b*HH + h);
                float val = f2tff(acc[mat][nt][u] * sc);
                if (mat == 0) {
                    if (isQ)  g_q[(bh*LL + slot)*DKK + permk(dk)] = val;
                } else if (mat == 1) {
                    if (!isQ) g_k[(bh*LL + slot)*DKK + permk(dk)] = val;
                } else {
                    if (!isQ) g_v[bh*(LL*DKK) + (slot>>3)*256 + dk*8 + (slot&7)] = val;
                }
            }
        }
    }
}

// ---------------------------------------------------------------------------
// Kernel B: compacted flash attention. 64-row q-tiles, 128 thr / 4 warps,
// KEY-SPLIT: warp w = (row-half w>>1) x (key-half w&1). Each warp: 32 rows
// (2 strips) x 32 keys -> every K/V fragment feeds 2 mmas. O/l combined
// across key-halves through smem (aliased over Ks/Vs) after the last tile.
// ---------------------------------------------------------------------------
struct ASmem {
    float Ks[2][64][40];    // 20480 B  (combine aliases comb[2][64][33] here)
    float Vs[2][2048];      // 16384 B  (combine aliases comb_l[2][64] here)
};

__global__ __launch_bounds__(128, 4) void attn_kernel()
{
    const int b = blockIdx.z, h = blockIdx.y, q0 = blockIdx.x * 64;
    const int cnt0 = g_cnt[2*b], cnt1 = g_cnt[2*b+1];
    const int npad1 = (cnt1 + 63) & ~63;
    if (q0 >= npad1) return;
    const int NT = (cnt0 + 63) >> 6;
    const float padcorr = (float)(NT*64 - cnt0) * P_PAD;

    __shared__ ASmem S;
    const int t = threadIdx.x, lane = t & 31, wid = t >> 5;
    const int g = lane >> 2, tg = lane & 3;
    const int kh = wid & 1;          // key half (keys kh*32 .. +31 of each tile)
    const int rh = wid >> 1;         // row half (rows rh*32 .. +31)
    const int r0 = rh * 32;

    const float* __restrict__ Qg = g_q + ((size_t)(b*HH+h))*LL*DKK;
    const float* __restrict__ Kg = g_k + ((size_t)(b*HH+h))*LL*DKK;
    const float* __restrict__ Vg = g_v + ((size_t)(b*HH+h))*LL*DKK;

    // Prefetch tile 0
    #pragma unroll
    for (int i = 0; i < 4; i++) {
        int ch = t + i*128;
        { int row = ch >> 3, off = (ch & 7)*4;
          cpa16(&S.Ks[0][row][off], Kg + row*DKK + off); }
        cpa16(&S.Vs[0][ch*4], Vg + ch*4);
    }
    cpa_commit();

    // Q fragments (2 strips of 16 rows)
    uint32_t aQ[2][4][4];
    #pragma unroll
    for (int s = 0; s < 2; s++)
        #pragma unroll
        for (int kg4 = 0; kg4 < 4; kg4++) {
            float2 x0 = *reinterpret_cast<const float2*>(
                &Qg[(q0 + r0 + s*16 + g    )*DKK + kg4*8 + 2*tg]);
            float2 x1 = *reinterpret_cast<const float2*>(
                &Qg[(q0 + r0 + s*16 + g + 8)*DKK + kg4*8 + 2*tg]);
            aQ[s][kg4][0] = __float_as_uint(x0.x);
            aQ[s][kg4][1] = __float_as_uint(x1.x);
            aQ[s][kg4][2] = __float_as_uint(x0.y);
            aQ[s][kg4][3] = __float_as_uint(x1.y);
        }

    float o[2][4][4] = {};
    float l[2][2] = {};

    for (int kt = 0; kt < NT; kt++) {
        const int d = kt & 1;
        __syncthreads();
        if (kt + 1 < NT) {
            const int c0n = (kt+1)*64, dn = (kt+1)&1;
            #pragma unroll
            for (int i = 0; i < 4; i++) {
                int ch = t + i*128;
                { int row = ch >> 3, off = (ch & 7)*4;
                  cpa16(&S.Ks[dn][row][off], Kg + (c0n+row)*DKK + off); }
                cpa16(&S.Vs[dn][ch*4], Vg + (kt+1)*2048 + ch*4);
            }
            cpa_commit();
            cpa_wait<1>();
        } else cpa_wait<0>();
        __syncthreads();

        // This warp's 4 key-groups: jg = kh*4 + j
        #pragma unroll
        for (int j = 0; j < 4; j++) {
            const int jg = kh*4 + j;
            float accS[2][4] = {};
            #pragma unroll
            for (int kg4 = 0; kg4 < 4; kg4++) {
                float2 bv = *reinterpret_cast<float2*>(&S.Ks[d][jg*8+g][kg4*8+2*tg]);
                mma8(accS[0], aQ[0][kg4], __float_as_uint(bv.x), __float_as_uint(bv.y));
                mma8(accS[1], aQ[1][kg4], __float_as_uint(bv.x), __float_as_uint(bv.y));
            }
            uint32_t aP[2][4];
            #pragma unroll
            for (int s = 0; s < 2; s++) {
                float p0 = ex2(accS[s][0]-SHIFT);
                float p1 = ex2(accS[s][1]-SHIFT);
                float p2 = ex2(accS[s][2]-SHIFT);
                float p3 = ex2(accS[s][3]-SHIFT);
                l[s][0] += p0 + p1;  l[s][1] += p2 + p3;
                aP[s][0] = __float_as_uint(p0);
                aP[s][1] = __float_as_uint(p2);
                aP[s][2] = __float_as_uint(p1);
                aP[s][3] = __float_as_uint(p3);
            }
            #pragma unroll
            for (int nt = 0; nt < 4; nt++) {
                float2 bv = *reinterpret_cast<float2*>(&S.Vs[d][jg*256 + (nt*8+g)*8 + 2*tg]);
                mma8(o[0][nt], aP[0], __float_as_uint(bv.x), __float_as_uint(bv.y));
                mma8(o[1][nt], aP[1], __float_as_uint(bv.x), __float_as_uint(bv.y));
            }
        }
    }

    // ---- reduce l within quad (per key-half) ----
    #pragma unroll
    for (int s = 0; s < 2; s++) {
        l[s][0] += __shfl_xor_sync(~0u, l[s][0], 1);
        l[s][0] += __shfl_xor_sync(~0u, l[s][0], 2);
        l[s][1] += __shfl_xor_sync(~0u, l[s][1], 1);
        l[s][1] += __shfl_xor_sync(~0u, l[s][1], 2);
    }

    // ---- combine key-halves through smem (alias over Ks / Vs) ----
    __syncthreads();    // all warps done reading Ks/Vs
    float (*comb)[64][33] = reinterpret_cast<float (*)[64][33]>(&S.Ks[0][0][0]);
    float* comb_l = reinterpret_cast<float*>(&S.Vs[0][0]);   // [2][64]
    #pragma unroll
    for (int s = 0; s < 2; s++) {
        int rr = r0 + s*16 + g;
        #pragma unroll
        for (int nt = 0; nt < 4; nt++) {
            comb[kh][rr  ][nt*8+2*tg  ] = o[s][nt][0];
            comb[kh][rr  ][nt*8+2*tg+1] = o[s][nt][1];
            comb[kh][rr+8][nt*8+2*tg  ] = o[s][nt][2];
            comb[kh][rr+8][nt*8+2*tg+1] = o[s][nt][3];
        }
        if (tg == 0) {
            comb_l[kh*64 + rr    ] = l[s][0];
            comb_l[kh*64 + rr + 8] = l[s][1];
        }
    }
    __syncthreads();

    // ---- epilogue: add halves, /l, scatter via idx1 ----
    {
        int r   = t >> 1;
        int dk0 = (t & 1) * 16;
        int rq  = q0 + r;
        if (rq < cnt1) {
            float lt  = comb_l[r] + comb_l[64 + r] - padcorr;
            float inv = 1.0f / lt;
            int lq = g_idx1[b*LL + rq];
            float* __restrict__ H = &g_head[((size_t)(b*LL + lq))*DD + h*DKK + dk0];
            #pragma unroll
            for (int u = 0; u < 4; u++) {
                float4 o4;
                o4.x = f2tff((comb[0][r][dk0+u*4+0] + comb[1][r][dk0+u*4+0]) * inv);
                o4.y = f2tff((comb[0][r][dk0+u*4+1] + comb[1][r][dk0+u*4+1]) * inv);
                o4.z = f2tff((comb[0][r][dk0+u*4+2] + comb[1][r][dk0+u*4+2]) * inv);
                o4.w = f2tff((comb[0][r][dk0+u*4+3] + comb[1][r][dk0+u*4+3]) * inv);
                *reinterpret_cast<float4*>(H + u*4) = o4;
            }
        }
    }
}

// ---------------------------------------------------------------------------
// Kernel C: output projection (R15 config).
// ---------------------------------------------------------------------------
struct OSmem {
    float    As[2][128][36];
    uint32_t Bs[128][72];
};
extern __shared__ uint32_t osm_u[];

__global__ __launch_bounds__(256, 3) void out_kernel(
    const float* __restrict__ Wo, float* __restrict__ out)
{
    OSmem& S = *reinterpret_cast<OSmem*>(osm_u);
    const int half = blockIdx.x;
    const int m0   = blockIdx.y * 128;
    const int b    = m0 >> 11;
    const int l0   = m0 & 2047;
    const int t    = threadIdx.x;
    const int lane = t & 31, wid = t >> 5;
    const int g = lane >> 2, tg = lane & 3, r0 = wid * 16;

    #pragma unroll
    for (int i = 0; i < 8; i++) {
        int fid = t + i*256;
        int n4 = fid & 15, kk = fid >> 4;
        float4 v4 = *reinterpret_cast<const float4*>(&Wo[kk*DD + half*64 + n4*4]);
        uint4 u; u.x=f2tf(v4.x); u.y=f2tf(v4.y); u.z=f2tf(v4.z); u.w=f2tf(v4.w);
        *reinterpret_cast<uint4*>(&S.Bs[kk][n4*4]) = u;
    }
    #pragma unroll
    for (int i = 0; i < 4; i++) {
        int ch = t + i*256;
        int mm = ch >> 3, off = (ch & 7)*4;
        cpa16(&S.As[0][mm][off], &g_head[(((size_t)(b*LL)) + l0 + mm)*DD + off]);
    }
    cpa_commit();
    __syncthreads();

    float acc[8][4] = {};
    for (int c4 = 0; c4 < 4; c4++) {
        const int dbuf = c4 & 1;
        if (c4) __syncthreads();
        if (c4 + 1 < 4) {
            int k0n = (c4+1)*32, dn = (c4+1)&1;
            #pragma unroll
            for (int i = 0; i < 4; i++) {
                int ch = t + i*256;
                int mm = ch >> 3, off = (ch & 7)*4;
                cpa16(&S.As[dn][mm][off],
                      &g_head[(((size_t)(b*LL)) + l0 + mm)*DD + k0n + off]);
            }
            cpa_commit();
            cpa_wait<1>();
        } else cpa_wait<0>();
        __syncthreads();

        #pragma unroll
        for (int kg4 = 0; kg4 < 4; kg4++) {
            const int kr = kg4*8;
            uint32_t a[4] = {__float_as_uint(S.As[dbuf][r0+g  ][kr+tg]),
                             __float_as_uint(S.As[dbuf][r0+g+8][kr+tg]),
                             __float_as_uint(S.As[dbuf][r0+g  ][kr+tg+4]),
                             __float_as_uint(S.As[dbuf][r0+g+8][kr+tg+4])};
            #pragma unroll
            for (int nt = 0; nt < 8; nt++)
                mma8(acc[nt], a, S.Bs[c4*32+kr+tg][nt*8+g],
                                 S.Bs[c4*32+kr+tg+4][nt*8+g]);
        }
    }
    __syncthreads();

    float (*Cs)[132] = reinterpret_cast<float (*)[132]>(&S.As[0][0][0]);
    #pragma unroll
    for (int nt = 0; nt < 8; nt++) {
        Cs[nt*8+2*tg  ][r0+g  ] = acc[nt][0];
        Cs[nt*8+2*tg+1][r0+g  ] = acc[nt][1];
        Cs[nt*8+2*tg  ][r0+g+8] = acc[nt][2];
        Cs[nt*8+2*tg+1][r0+g+8] = acc[nt][3];
    }
    __syncthreads();
    #pragma unroll
    for (int i = 0; i < 8; i++) {
        int fid = t + i*256;
        int m4 = fid & 31, nn = fid >> 5;
        float4 v4 = *reinterpret_cast<const float4*>(&Cs[nn][m4*4]);
        *reinterpret_cast<float4*>(
            &out[((size_t)(b*DD + half*64 + nn))*LL + l0 + m4*4]) = v4;
    }
}

// ---------------------------------------------------------------------------
extern "C" void kernel_launch(void* const* d_in, const int* in_sizes, int n_in,
                              void* d_out, int out_size)
{
    const float* x    = (const float*)d_in[0];
    const float* mask = (const float*)d_in[1];
    const float* Wq   = (const float*)d_in[2];
    const float* Wk   = (const float*)d_in[3];
    const float* Wv   = (const float*)d_in[4];
    const float* Wo   = (const float*)d_in[5];
    float* out = (float*)d_out;

    scan_kernel<<<BB, 256>>>(mask);
    conv_kernel<<<(BB*DD*LL)/4/256, 256>>>(x, mask);

    cudaFuncSetAttribute(qkv_kernel, cudaFuncAttributeMaxDynamicSharedMemorySize,
                         (int)sizeof(QSmem));
    dim3 gA(2, (BB*LL)/128);
    qkv_kernel<<<gA, 256, sizeof(QSmem)>>>(Wq, Wk, Wv, mask);

    dim3 gB(LL/64, HH, BB);
    attn_kernel<<<gB, 128>>>();

    cudaFuncSetAttribute(out_kernel, cudaFuncAttributeMaxDynamicSharedMemorySize,
                         (int)sizeof(OSmem));
    dim3 gC(2, (BB*LL)/128);
    out_kernel<<<gC, 256, sizeof(OSmem)>>>(Wo, out);
}